// round 13
// baseline (speedup 1.0000x reference)
#include <cuda_runtime.h>

#define NHEAD 8
#define HD 64
#define DMODEL 512
#define NP 16
#define NB 2
#define NT 2048
#define NVOC 16
#define NTOK (NB*NT)        // 4096
#define NTH (NTOK*NHEAD)    // 32768

#define STR 72    // bf16 halfs per smem plane row
#define WSTR 36   // 32-bit words per row
#define PLH (64*STR)

// ---------------- scratch ----------------
__device__ float g_h[NTOK*DMODEL];
__device__ float g_q[NTH*HD];     // [bh][t][64]
__device__ float g_k[NTH*HD];
__device__ float g_v[NTH*HD];
__device__ float g_attn[NTH*HD];  // [token][head][64]
__device__ float g_C[DMODEL*NVOC];
__device__ float g_E16[NVOC*NVOC];   // embed @ head_w^T
// weight planes: [plane(W1h,W1l,W2h,W2l)][expert][64][64] bf16
__device__ unsigned short g_wplanes[4*NP*4096];

__device__ __forceinline__ void split2(float x0, float x1, unsigned &h, unsigned &l) {
    asm("cvt.rn.bf16x2.f32 %0, %1, %2;" : "=r"(h) : "f"(x1), "f"(x0));
    float h0 = __uint_as_float(h << 16);
    float h1 = __uint_as_float(h & 0xffff0000u);
    asm("cvt.rn.bf16x2.f32 %0, %1, %2;" : "=r"(l) : "f"(x1 - h1), "f"(x0 - h0));
}

__device__ __forceinline__ void mma_bf16(float* c, unsigned a0, unsigned a1,
                                         unsigned a2, unsigned a3,
                                         unsigned b0, unsigned b1) {
    asm volatile(
        "mma.sync.aligned.m16n8k16.row.col.f32.bf16.bf16.f32 "
        "{%0,%1,%2,%3}, {%4,%5,%6,%7}, {%8,%9}, {%0,%1,%2,%3};\n"
        : "+f"(c[0]), "+f"(c[1]), "+f"(c[2]), "+f"(c[3])
        : "r"(a0), "r"(a1), "r"(a2), "r"(a3), "r"(b0), "r"(b1));
}
__device__ __forceinline__ void mma3(float* c, const unsigned* ah, const unsigned* al,
                                     unsigned b0h, unsigned b1h,
                                     unsigned b0l, unsigned b1l) {
    mma_bf16(c, al[0], al[1], al[2], al[3], b0h, b1h);
    mma_bf16(c, ah[0], ah[1], ah[2], ah[3], b0l, b1l);
    mma_bf16(c, ah[0], ah[1], ah[2], ah[3], b0h, b1h);
}
__device__ __forceinline__ void ldm_x4(unsigned* r, const unsigned short* p) {
    unsigned a = (unsigned)__cvta_generic_to_shared(p);
    asm volatile("ldmatrix.sync.aligned.m8n8.x4.shared.b16 {%0,%1,%2,%3}, [%4];"
                 : "=r"(r[0]), "=r"(r[1]), "=r"(r[2]), "=r"(r[3]) : "r"(a));
}
__device__ __forceinline__ void ldm_x4_t(unsigned* r, const unsigned short* p) {
    unsigned a = (unsigned)__cvta_generic_to_shared(p);
    asm volatile("ldmatrix.sync.aligned.m8n8.x4.trans.shared.b16 {%0,%1,%2,%3}, [%4];"
                 : "=r"(r[0]), "=r"(r[1]), "=r"(r[2]), "=r"(r[3]) : "r"(a));
}
__device__ __forceinline__ void cpa16(const void* smem_dst, const void* gmem_src) {
    unsigned a = (unsigned)__cvta_generic_to_shared(smem_dst);
    asm volatile("cp.async.cg.shared.global [%0], [%1], 16;" :: "r"(a), "l"(gmem_src));
}
#define CP_COMMIT() asm volatile("cp.async.commit_group;" ::)
#define CP_WAIT1()  asm volatile("cp.async.wait_group 1;" ::)
#define CP_WAIT0()  asm volatile("cp.async.wait_group 0;" ::)

__device__ __forceinline__ float fast_exp2(float x) {
    float r;
    asm("ex2.approx.f32 %0, %1;" : "=f"(r) : "f"(x));
    return r;
}

// ---------------- K0: C = o_w^T @ head_w^T  (blocks 0,1)  +  E16 = embed @ head_w^T (block 2)
__global__ __launch_bounds__(256) void k_prep_cn(const float* __restrict__ o_w,
                                                 const float* __restrict__ head_w,
                                                 const float* __restrict__ embed) {
    int tid = threadIdx.x;
    if (blockIdx.x < 2) {
        int d = blockIdx.x * 256 + tid;
        float acc[16];
        #pragma unroll
        for (int v = 0; v < 16; ++v) acc[v] = 0.f;
        #pragma unroll 4
        for (int e = 0; e < DMODEL; ++e) {
            float ow = o_w[(size_t)e * DMODEL + d];
            #pragma unroll
            for (int v = 0; v < 16; ++v)
                acc[v] += ow * __ldg(head_w + (size_t)v * DMODEL + e);
        }
        #pragma unroll
        for (int v = 0; v < 16; ++v)
            g_C[d * NVOC + v] = acc[v];
    } else {
        int w = tid >> 4, v = tid & 15;
        float acc = 0.f;
        #pragma unroll 8
        for (int d = 0; d < DMODEL; ++d)
            acc += embed[(size_t)w * DMODEL + d] * head_w[(size_t)v * DMODEL + d];
        g_E16[w * NVOC + v] = acc;
    }
}

// ---------------- K0b: pre-split w1/w2 into bf16 planes ----------------
__global__ __launch_bounds__(256) void k_prep_w(const float* __restrict__ w1,
                                                const float* __restrict__ w2) {
    int i = blockIdx.x * blockDim.x + threadIdx.x;
    if (i >= NP * 2048) return;
    unsigned* wp = (unsigned*)g_wplanes;
    float2 a = ((const float2*)w1)[i];
    unsigned h, l;
    split2(a.x, a.y, h, l);
    wp[0 * NP * 2048 + i] = h;
    wp[1 * NP * 2048 + i] = l;
    float2 b = ((const float2*)w2)[i];
    split2(b.x, b.y, h, l);
    wp[2 * NP * 2048 + i] = h;
    wp[3 * NP * 2048 + i] = l;
}

// ---------------- K1: embedding + layernorm (residual folded into E16; no g_x store) ----------------
__global__ __launch_bounds__(128) void k_embed_ln(
    const int* __restrict__ ids, const float* __restrict__ embed,
    const float* __restrict__ lng, const float* __restrict__ lnb) {
    int t = blockIdx.x;
    int tid = threadIdx.x;
    const float4* row = (const float4*)(embed + (size_t)ids[t] * DMODEL);
    float4 xv = row[tid];
    float s  = xv.x + xv.y + xv.z + xv.w;
    float s2 = xv.x*xv.x + xv.y*xv.y + xv.z*xv.z + xv.w*xv.w;
    #pragma unroll
    for (int o = 16; o; o >>= 1) {
        s  += __shfl_xor_sync(0xffffffffu, s, o);
        s2 += __shfl_xor_sync(0xffffffffu, s2, o);
    }
    __shared__ float sh[8];
    int w = tid >> 5;
    if ((tid & 31) == 0) { sh[w] = s; sh[4 + w] = s2; }
    __syncthreads();
    s  = sh[0] + sh[1] + sh[2] + sh[3];
    s2 = sh[4] + sh[5] + sh[6] + sh[7];
    float mu  = s * (1.0f / DMODEL);
    float var = s2 * (1.0f / DMODEL) - mu * mu;
    float inv = rsqrtf(var + 1e-5f);
    float4 gv = ((const float4*)lng)[tid];
    float4 bv = ((const float4*)lnb)[tid];
    float4 hv;
    hv.x = (xv.x - mu) * inv * gv.x + bv.x;
    hv.y = (xv.y - mu) * inv * gv.y + bv.y;
    hv.z = (xv.z - mu) * inv * gv.z + bv.z;
    hv.w = (xv.w - mu) * inv * gv.w + bv.w;
    ((float4*)(g_h + (size_t)t * DMODEL))[tid] = hv;
}

// ---------------- K2: compose via bf16 two-plane mma ----------------
// 256 threads = 8 warps (4 row-groups x 2 n-halves). 64 rows/block.
// 3-phase cp.async pipeline: W2(p) fill overlaps GEMM1(p); W1(p+1) overlaps GEMM2(p).
__global__ __launch_bounds__(256, 2) void k_compose(
    const float* __restrict__ pq, const float* __restrict__ gq,
    const float* __restrict__ pk, const float* __restrict__ gk,
    const float* __restrict__ pv, const float* __restrict__ gv) {
    extern __shared__ __align__(16) unsigned short smc[];
    unsigned short* Xh  = smc;               // 64 x 72
    unsigned short* Xl  = Xh  + PLH;
    unsigned short* W1h = Xl  + PLH;
    unsigned short* W1l = W1h + PLH;
    unsigned short* W2h = W1l + PLH;
    unsigned short* W2l = W2h + PLH;
    unsigned short* Sh  = W2l + PLH;
    unsigned short* Sl  = Sh  + PLH;
    float* WG = (float*)(Sl + PLH);          // 3 x 64 x 16

    const int tid = threadIdx.x, warp = tid >> 5, lane = tid & 31;
    const int g = lane >> 2, tg = lane & 3;
    const int mi0 = (lane >> 3) & 1;
    const int mi1 = lane >> 4;
    const int r8 = lane & 7;
    const int wy = warp >> 1, wx = warp & 1;
    const int wr0 = wy * 16, nc0 = wx * 32;
    const int row0 = blockIdx.x * 64;

    unsigned* Xhw = (unsigned*)Xh; unsigned* Xlw = (unsigned*)Xl;
    unsigned* Shw = (unsigned*)Sh; unsigned* Slw = (unsigned*)Sl;

    auto load_w1 = [&](int p) {
        #pragma unroll
        for (int i = tid; i < 1024; i += 256) {
            int plane = i >> 9, j = i & 511;
            int r = j >> 3, c = j & 7;
            cpa16((plane ? W1l : W1h) + r * STR + c * 8,
                  g_wplanes + (size_t)(plane * NP + p) * 4096 + r * 64 + c * 8);
        }
        CP_COMMIT();
    };
    auto load_w2 = [&](int p) {
        #pragma unroll
        for (int i = tid; i < 1024; i += 256) {
            int plane = i >> 9, j = i & 511;
            int r = j >> 3, c = j & 7;
            cpa16((plane ? W2l : W2h) + r * STR + c * 8,
                  g_wplanes + (size_t)((2 + plane) * NP + p) * 4096 + r * 64 + c * 8);
        }
        CP_COMMIT();
    };

    load_w1(0);
    load_w2(0);

    // fill X planes
    #pragma unroll
    for (int i = tid; i < 64 * 16; i += 256) {
        int r = i >> 4, c = i & 15;
        float4 v = ((const float4*)(g_h + (size_t)(row0 + r) * 64))[c];
        unsigned h0, l0, h1, l1;
        split2(v.x, v.y, h0, l0);
        split2(v.z, v.w, h1, l1);
        Xhw[r * WSTR + 2 * c] = h0; Xhw[r * WSTR + 2 * c + 1] = h1;
        Xlw[r * WSTR + 2 * c] = l0; Xlw[r * WSTR + 2 * c + 1] = l1;
    }

    // gate weights
    for (int i = tid; i < 64 * 16; i += 256) {
        int r = i >> 4, p = i & 15;
        const float* xr = g_h + (size_t)(row0 + r) * 64;
        float dq = 0.f, dk = 0.f, dv = 0.f;
        #pragma unroll 8
        for (int d = 0; d < 64; ++d) {
            float xv = __ldg(xr + d);
            dq += xv * pq[p * 64 + d];
            dk += xv * pk[p * 64 + d];
            dv += xv * pv[p * 64 + d];
        }
        float lq = dq * 0.125f - gq[p];
        float lk = dk * 0.125f - gk[p];
        float lv = dv * 0.125f - gv[p];
        WG[(0 * 64 + r) * 16 + p] = lq > 1e-6f ? lq : 0.f;
        WG[(1 * 64 + r) * 16 + p] = lk > 1e-6f ? lk : 0.f;
        WG[(2 * 64 + r) * 16 + p] = lv > 1e-6f ? lv : 0.f;
    }

    float aq[16], ak[16], av[16];
    #pragma unroll
    for (int i = 0; i < 16; ++i) { aq[i] = 0.f; ak[i] = 0.f; av[i] = 0.f; }

    const float LOG2E = 1.44269504f;

    for (int p = 0; p < NP; ++p) {
        CP_WAIT1();        // W1(p) complete; W2(p) may still be in flight
        __syncthreads();

        // GEMM1: H = X @ W1^T  (warp: 16 rows x 32 cols); A-frags via ldmatrix
        float hb[16];
        #pragma unroll
        for (int i = 0; i < 16; ++i) hb[i] = 0.f;
        #pragma unroll
        for (int ks = 0; ks < 4; ++ks) {
            unsigned ah[4], al[4];
            int aoff = (wr0 + mi0 * 8 + r8) * STR + ks * 16 + mi1 * 8;
            ldm_x4(ah, Xh + aoff);
            ldm_x4(al, Xl + aoff);
            #pragma unroll
            for (int np = 0; np < 2; ++np) {
                int roff = (nc0 + np * 16 + mi1 * 8 + r8) * STR + ks * 16 + mi0 * 8;
                unsigned bh[4], bl[4];
                ldm_x4(bh, W1h + roff);
                ldm_x4(bl, W1l + roff);
                mma3(&hb[(np * 2) * 4],     ah, al, bh[0], bh[1], bl[0], bl[1]);
                mma3(&hb[(np * 2 + 1) * 4], ah, al, bh[2], bh[3], bl[2], bl[3]);
            }
        }
        // silu -> S planes
        #pragma unroll
        for (int nt = 0; nt < 4; ++nt) {
            #pragma unroll
            for (int j = 0; j < 4; ++j) {
                float h = hb[nt * 4 + j];
                hb[nt * 4 + j] = h / (1.f + fast_exp2(-h * LOG2E));
            }
            unsigned h0, l0;
            split2(hb[nt * 4 + 0], hb[nt * 4 + 1], h0, l0);
            Shw[(wr0 + g) * WSTR + nc0 / 2 + 4 * nt + tg] = h0;
            Slw[(wr0 + g) * WSTR + nc0 / 2 + 4 * nt + tg] = l0;
            split2(hb[nt * 4 + 2], hb[nt * 4 + 3], h0, l0);
            Shw[(wr0 + g + 8) * WSTR + nc0 / 2 + 4 * nt + tg] = h0;
            Slw[(wr0 + g + 8) * WSTR + nc0 / 2 + 4 * nt + tg] = l0;
        }
        CP_WAIT0();        // W2(p) complete
        __syncthreads();   // S visible, W2 visible, W1 free
        if (p + 1 < NP) load_w1(p + 1);   // overlaps GEMM2

        // GEMM2: out = silu(H) @ W2^T; A-frags via ldmatrix
        float ob[16];
        #pragma unroll
        for (int i = 0; i < 16; ++i) ob[i] = 0.f;
        #pragma unroll
        for (int ks = 0; ks < 4; ++ks) {
            unsigned ah[4], al[4];
            int aoff = (wr0 + mi0 * 8 + r8) * STR + ks * 16 + mi1 * 8;
            ldm_x4(ah, Sh + aoff);
            ldm_x4(al, Sl + aoff);
            #pragma unroll
            for (int np = 0; np < 2; ++np) {
                int roff = (nc0 + np * 16 + mi1 * 8 + r8) * STR + ks * 16 + mi0 * 8;
                unsigned bh[4], bl[4];
                ldm_x4(bh, W2h + roff);
                ldm_x4(bl, W2l + roff);
                mma3(&ob[(np * 2) * 4],     ah, al, bh[0], bh[1], bl[0], bl[1]);
                mma3(&ob[(np * 2 + 1) * 4], ah, al, bh[2], bh[3], bl[2], bl[3]);
            }
        }
        // gated accumulate
        float wq0 = WG[(0 * 64 + wr0 + g)     * 16 + p];
        float wq1 = WG[(0 * 64 + wr0 + g + 8) * 16 + p];
        float wk0 = WG[(1 * 64 + wr0 + g)     * 16 + p];
        float wk1 = WG[(1 * 64 + wr0 + g + 8) * 16 + p];
        float wv0 = WG[(2 * 64 + wr0 + g)     * 16 + p];
        float wv1 = WG[(2 * 64 + wr0 + g + 8) * 16 + p];
        #pragma unroll
        for (int nt = 0; nt < 4; ++nt) {
            aq[nt*4+0] += wq0 * ob[nt*4+0]; aq[nt*4+1] += wq0 * ob[nt*4+1];
            aq[nt*4+2] += wq1 * ob[nt*4+2]; aq[nt*4+3] += wq1 * ob[nt*4+3];
            ak[nt*4+0] += wk0 * ob[nt*4+0]; ak[nt*4+1] += wk0 * ob[nt*4+1];
            ak[nt*4+2] += wk1 * ob[nt*4+2]; ak[nt*4+3] += wk1 * ob[nt*4+3];
            av[nt*4+0] += wv0 * ob[nt*4+0]; av[nt*4+1] += wv0 * ob[nt*4+1];
            av[nt*4+2] += wv1 * ob[nt*4+2]; av[nt*4+3] += wv1 * ob[nt*4+3];
        }
        __syncthreads();   // W2/S free
        if (p + 1 < NP) load_w2(p + 1);   // overlaps next GEMM1
    }

    // write q,k,v to [bh][t][64]
    int r_lo = row0 + wr0 + g;
    int r_hi = r_lo + 8;
    int tok_lo = r_lo >> 3, h_lo = r_lo & 7;
    int tok_hi = r_hi >> 3, h_hi = r_hi & 7;
    int b_lo = tok_lo >> 11, t_lo = tok_lo & 2047;
    int b_hi = tok_hi >> 11, t_hi = tok_hi & 2047;
    size_t base_lo = ((size_t)(b_lo * 8 + h_lo) * NT + t_lo) * 64;
    size_t base_hi = ((size_t)(b_hi * 8 + h_hi) * NT + t_hi) * 64;
    #pragma unroll
    for (int nt = 0; nt < 4; ++nt) {
        int col = nc0 + nt * 8 + 2 * tg;
        *(float2*)&g_q[base_lo + col] = make_float2(aq[nt*4+0], aq[nt*4+1]);
        *(float2*)&g_q[base_hi + col] = make_float2(aq[nt*4+2], aq[nt*4+3]);
        *(float2*)&g_k[base_lo + col] = make_float2(ak[nt*4+0], ak[nt*4+1]);
        *(float2*)&g_k[base_hi + col] = make_float2(ak[nt*4+2], ak[nt*4+3]);
        *(float2*)&g_v[base_lo + col] = make_float2(av[nt*4+0], av[nt*4+1]);
        *(float2*)&g_v[base_hi + col] = make_float2(av[nt*4+2], av[nt*4+3]);
    }
}

// ---------------- K3: flash attention via bf16 two-plane mma ----------------
// 128 threads = 4 warps x 16 q rows; 64-row Q tile, 64-row K tile.
__global__ __launch_bounds__(128) void k_attn() {
    extern __shared__ __align__(16) unsigned short sma[];
    unsigned short* Kh = sma;
    unsigned short* Kl = Kh + PLH;
    unsigned short* Vh = Kl + PLH;
    unsigned short* Vl = Vh + PLH;
    unsigned* Khw = (unsigned*)Kh; unsigned* Klw = (unsigned*)Kl;
    unsigned* Vhw = (unsigned*)Vh; unsigned* Vlw = (unsigned*)Vl;

    const int tid = threadIdx.x, warp = tid >> 5, lane = tid & 31;
    const int g = lane >> 2, tg = lane & 3;
    const int mi0 = (lane >> 3) & 1;
    const int mi1 = lane >> 4;
    const int r8 = lane & 7;
    const int qtile = 31 - blockIdx.x;
    const int qt0 = qtile * 64;
    const int bh = blockIdx.y;
    const int b = bh >> 3, h = bh & 7;
    const float* qbase = g_q + (size_t)bh * NT * 64;
    const float* kbase = g_k + (size_t)bh * NT * 64;
    const float* vbase = g_v + (size_t)bh * NT * 64;
    const int wr0 = warp * 16;

    unsigned Qh[4][4], Ql[4][4];
    {
        const float* qr0 = qbase + (size_t)(qt0 + wr0 + g) * 64 + 2 * tg;
        const float* qr1 = qbase + (size_t)(qt0 + wr0 + g + 8) * 64 + 2 * tg;
        #pragma unroll
        for (int ks = 0; ks < 4; ++ks) {
            float2 v;
            v = *(const float2*)(qr0 + 16 * ks);     split2(v.x, v.y, Qh[ks][0], Ql[ks][0]);
            v = *(const float2*)(qr1 + 16 * ks);     split2(v.x, v.y, Qh[ks][1], Ql[ks][1]);
            v = *(const float2*)(qr0 + 16 * ks + 8); split2(v.x, v.y, Qh[ks][2], Ql[ks][2]);
            v = *(const float2*)(qr1 + 16 * ks + 8); split2(v.x, v.y, Qh[ks][3], Ql[ks][3]);
        }
    }

    float O[32];
    #pragma unroll
    for (int i = 0; i < 32; ++i) O[i] = 0.f;
    float m2[2] = {-1e30f, -1e30f};
    float l2[2] = {0.f, 0.f};
    const float sc = 0.125f * 1.44269504f;

    for (int kt = 0; kt <= qtile; ++kt) {
        __syncthreads();
        #pragma unroll
        for (int i = tid; i < 64 * 16; i += 128) {
            int r = i >> 4, c = i & 15;
            size_t base = (size_t)(kt * 64 + r) * 64 + 4 * c;
            float4 kv = *(const float4*)(kbase + base);
            float4 vv = *(const float4*)(vbase + base);
            unsigned h0, l0, h1, l1;
            split2(kv.x, kv.y, h0, l0); split2(kv.z, kv.w, h1, l1);
            Khw[r * WSTR + 2 * c] = h0; Khw[r * WSTR + 2 * c + 1] = h1;
            Klw[r * WSTR + 2 * c] = l0; Klw[r * WSTR + 2 * c + 1] = l1;
            split2(vv.x, vv.y, h0, l0); split2(vv.z, vv.w, h1, l1);
            Vhw[r * WSTR + 2 * c] = h0; Vhw[r * WSTR + 2 * c + 1] = h1;
            Vlw[r * WSTR + 2 * c] = l0; Vlw[r * WSTR + 2 * c + 1] = l1;
        }
        __syncthreads();

        const bool diag = (kt == qtile);
        const int npmax = diag ? warp : 3;

        float s[32];
        #pragma unroll
        for (int i = 0; i < 32; ++i) s[i] = 0.f;
        #pragma unroll
        for (int ks = 0; ks < 4; ++ks) {
            for (int np = 0; np <= npmax; ++np) {
                int roff = (np * 16 + mi1 * 8 + r8) * STR + ks * 16 + mi0 * 8;
                unsigned bh4[4], bl4[4];
                ldm_x4(bh4, Kh + roff);
                ldm_x4(bl4, Kl + roff);
                mma3(&s[(np * 2) * 4],     Qh[ks], Ql[ks], bh4[0], bh4[1], bl4[0], bl4[1]);
                mma3(&s[(np * 2 + 1) * 4], Qh[ks], Ql[ks], bh4[2], bh4[3], bl4[2], bl4[3]);
            }
        }
        #pragma unroll
        for (int nt = 0; nt < 8; ++nt)
            #pragma unroll
            for (int j = 0; j < 4; ++j) {
                int rr = qt0 + wr0 + g + (j >> 1) * 8;
                int cc = kt * 64 + nt * 8 + 2 * tg + (j & 1);
                float v = s[nt * 4 + j] * sc;
                if (diag && cc > rr) v = -1e30f;
                s[nt * 4 + j] = v;
            }
        #pragma unroll
        for (int h2 = 0; h2 < 2; ++h2) {
            float mx = -1e30f;
            #pragma unroll
            for (int nt = 0; nt < 8; ++nt) {
                mx = fmaxf(mx, s[nt * 4 + h2 * 2 + 0]);
                mx = fmaxf(mx, s[nt * 4 + h2 * 2 + 1]);
            }
            mx = fmaxf(mx, __shfl_xor_sync(0xffffffffu, mx, 1));
            mx = fmaxf(mx, __shfl_xor_sync(0xffffffffu, mx, 2));
            float mn = fmaxf(m2[h2], mx);
            float alpha = fast_exp2(m2[h2] - mn);
            m2[h2] = mn;
            float rs = 0.f;
            #pragma unroll
            for (int nt = 0; nt < 8; ++nt) {
                float p0 = fast_exp2(s[nt * 4 + h2 * 2 + 0] - mn);
                float p1 = fast_exp2(s[nt * 4 + h2 * 2 + 1] - mn);
                s[nt * 4 + h2 * 2 + 0] = p0;
                s[nt * 4 + h2 * 2 + 1] = p1;
                rs += p0 + p1;
            }
            rs += __shfl_xor_sync(0xffffffffu, rs, 1);
            rs += __shfl_xor_sync(0xffffffffu, rs, 2);
            l2[h2] = l2[h2] * alpha + rs;
            #pragma unroll
            for (int nt = 0; nt < 8; ++nt) {
                O[nt * 4 + h2 * 2 + 0] *= alpha;
                O[nt * 4 + h2 * 2 + 1] *= alpha;
            }
        }
        const int ksmax = diag ? warp : 3;
        #pragma unroll
        for (int ks = 0; ks < 4; ++ks) {
            if (ks > ksmax) break;
            unsigned pah[4], pal[4];
            split2(s[8 * ks + 0], s[8 * ks + 1], pah[0], pal[0]);
            split2(s[8 * ks + 2], s[8 * ks + 3], pah[1], pal[1]);
            split2(s[8 * ks + 4], s[8 * ks + 5], pah[2], pal[2]);
            split2(s[8 * ks + 6], s[8 * ks + 7], pah[3], pal[3]);
            #pragma unroll
            for (int np = 0; np < 4; ++np) {
                int roff = (ks * 16 + mi0 * 8 + r8) * STR + np * 16 + mi1 * 8;
                unsigned vh4[4], vl4[4];
                ldm_x4_t(vh4, Vh + roff);
                ldm_x4_t(vl4, Vl + roff);
                mma3(&O[(np * 2) * 4],     pah, pal, vh4[0], vh4[1], vl4[0], vl4[1]);
                mma3(&O[(np * 2 + 1) * 4], pah, pal, vh4[2], vh4[3], vl4[2], vl4[3]);
            }
        }
    }

    float inv0 = 1.f / l2[0];
    float inv1 = 1.f / l2[1];
    int r_lo = qt0 + wr0 + g;
    int r_hi = r_lo + 8;
    size_t base_lo = ((size_t)(b * NT + r_lo) * 8 + h) * 64;
    size_t base_hi = ((size_t)(b * NT + r_hi) * 8 + h) * 64;
    #pragma unroll
    for (int nt = 0; nt < 8; ++nt) {
        int col = nt * 8 + 2 * tg;
        *(float2*)&g_attn[base_lo + col] =
            make_float2(O[nt*4+0] * inv0, O[nt*4+1] * inv0);
        *(float2*)&g_attn[base_hi + col] =
            make_float2(O[nt*4+2] * inv1, O[nt*4+3] * inv1);
    }
}

// ---------------- K4: logits[t] = E16[ids[t]] + attn_row @ C ----------------
// 8 tokens/block; C in smem (17-stride, conflict-free); shfl reduction.
__global__ __launch_bounds__(256) void k_final(const int* __restrict__ ids,
                                               float* __restrict__ out) {
    __shared__ float Cs[DMODEL * 17];   // 34816 B
    __shared__ float xa[DMODEL];
    int tid = threadIdx.x;
    for (int i = tid; i < DMODEL * NVOC; i += 256) {
        int d = i >> 4, v = i & 15;
        Cs[d * 17 + v] = g_C[i];
    }
    int v = tid >> 4, ch = tid & 15;
    int t0 = blockIdx.x * 8;
    __syncthreads();
    for (int tt = 0; tt < 8; ++tt) {
        int t = t0 + tt;
        for (int i = tid; i < DMODEL; i += 256)
            xa[i] = g_attn[(size_t)t * DMODEL + i];
        __syncthreads();
        float acc = 0.f;
        #pragma unroll
        for (int j = 0; j < 32; ++j) {
            int d = j * 16 + ch;
            acc += xa[d] * Cs[d * 17 + v];
        }
        acc += __shfl_xor_sync(0xffffffffu, acc, 1);
        acc += __shfl_xor_sync(0xffffffffu, acc, 2);
        acc += __shfl_xor_sync(0xffffffffu, acc, 4);
        acc += __shfl_xor_sync(0xffffffffu, acc, 8);
        if (ch == 0)
            out[(size_t)t * NVOC + v] = acc + g_E16[ids[t] * NVOC + v];
        __syncthreads();
    }
}

// ---------------- launch ----------------
extern "C" void kernel_launch(void* const* d_in, const int* in_sizes, int n_in,
                              void* d_out, int out_size) {
    const int*   ids    = (const int*)d_in[0];
    const float* embed  = (const float*)d_in[1];
    const float* ln_g   = (const float*)d_in[2];
    const float* ln_b   = (const float*)d_in[3];
    const float* pq     = (const float*)d_in[4];
    const float* gq     = (const float*)d_in[5];
    const float* pk     = (const float*)d_in[6];
    const float* gk     = (const float*)d_in[7];
    const float* pv     = (const float*)d_in[8];
    const float* gv     = (const float*)d_in[9];
    const float* w1     = (const float*)d_in[10];
    const float* w2     = (const float*)d_in[11];
    const float* o_w    = (const float*)d_in[12];
    const float* head_w = (const float*)d_in[13];
    float* out = (float*)d_out;

    const int smem_compose = 8 * PLH * 2 + 3 * 64 * 16 * 4;  // 86016
    const int smem_attn    = 4 * PLH * 2;                    // 36864
    cudaFuncSetAttribute(k_compose, cudaFuncAttributeMaxDynamicSharedMemorySize, smem_compose);
    cudaFuncSetAttribute(k_attn,    cudaFuncAttributeMaxDynamicSharedMemorySize, smem_attn);

    k_prep_cn<<<3, 256>>>(o_w, head_w, embed);
    k_prep_w<<<NP * 2048 / 256, 256>>>(w1, w2);
    k_embed_ln<<<NTOK, 128>>>(ids, embed, ln_g, ln_b);
    k_compose<<<NTH / 64, 256, smem_compose>>>(pq, gq, pk, gk, pv, gv);
    dim3 ag(NT / 64, NB * NHEAD);
    k_attn<<<ag, 128, smem_attn>>>();
    k_final<<<NTOK / 8, 256>>>(ids, out);
}

// round 15
// speedup vs baseline: 1.0087x; 1.0087x over previous
#include <cuda_runtime.h>

#define NHEAD 8
#define HD 64
#define DMODEL 512
#define NP 16
#define NB 2
#define NT 2048
#define NVOC 16
#define NTOK (NB*NT)        // 4096
#define NTH (NTOK*NHEAD)    // 32768

#define STR 72    // bf16 halfs per smem plane row
#define WSTR 36   // 32-bit words per row
#define PLH (64*STR)

// ---------------- scratch ----------------
__device__ float g_x[NTOK*DMODEL];
__device__ float g_h[NTOK*DMODEL];
__device__ float g_q[NTH*HD];     // [bh][t][64]
__device__ float g_k[NTH*HD];
__device__ float g_v[NTH*HD];
__device__ float g_attn[NTH*HD];  // [token][head][64]
__device__ float g_C[DMODEL*NVOC];
__device__ float g_E16[NVOC*NVOC];   // embed @ head_w^T
// weight planes: [plane(W1h,W1l,W2h,W2l)][expert][64][64] bf16
__device__ unsigned short g_wplanes[4*NP*4096];

__device__ __forceinline__ void split2(float x0, float x1, unsigned &h, unsigned &l) {
    asm("cvt.rn.bf16x2.f32 %0, %1, %2;" : "=r"(h) : "f"(x1), "f"(x0));
    float h0 = __uint_as_float(h << 16);
    float h1 = __uint_as_float(h & 0xffff0000u);
    asm("cvt.rn.bf16x2.f32 %0, %1, %2;" : "=r"(l) : "f"(x1 - h1), "f"(x0 - h0));
}

__device__ __forceinline__ void mma_bf16(float* c, unsigned a0, unsigned a1,
                                         unsigned a2, unsigned a3,
                                         unsigned b0, unsigned b1) {
    asm volatile(
        "mma.sync.aligned.m16n8k16.row.col.f32.bf16.bf16.f32 "
        "{%0,%1,%2,%3}, {%4,%5,%6,%7}, {%8,%9}, {%0,%1,%2,%3};\n"
        : "+f"(c[0]), "+f"(c[1]), "+f"(c[2]), "+f"(c[3])
        : "r"(a0), "r"(a1), "r"(a2), "r"(a3), "r"(b0), "r"(b1));
}
__device__ __forceinline__ void mma3(float* c, const unsigned* ah, const unsigned* al,
                                     unsigned b0h, unsigned b1h,
                                     unsigned b0l, unsigned b1l) {
    mma_bf16(c, al[0], al[1], al[2], al[3], b0h, b1h);
    mma_bf16(c, ah[0], ah[1], ah[2], ah[3], b0l, b1l);
    mma_bf16(c, ah[0], ah[1], ah[2], ah[3], b0h, b1h);
}
__device__ __forceinline__ void ldm_x4(unsigned* r, const unsigned short* p) {
    unsigned a = (unsigned)__cvta_generic_to_shared(p);
    asm volatile("ldmatrix.sync.aligned.m8n8.x4.shared.b16 {%0,%1,%2,%3}, [%4];"
                 : "=r"(r[0]), "=r"(r[1]), "=r"(r[2]), "=r"(r[3]) : "r"(a));
}
__device__ __forceinline__ void ldm_x4_t(unsigned* r, const unsigned short* p) {
    unsigned a = (unsigned)__cvta_generic_to_shared(p);
    asm volatile("ldmatrix.sync.aligned.m8n8.x4.trans.shared.b16 {%0,%1,%2,%3}, [%4];"
                 : "=r"(r[0]), "=r"(r[1]), "=r"(r[2]), "=r"(r[3]) : "r"(a));
}
__device__ __forceinline__ void cpa16(const void* smem_dst, const void* gmem_src) {
    unsigned a = (unsigned)__cvta_generic_to_shared(smem_dst);
    asm volatile("cp.async.cg.shared.global [%0], [%1], 16;" :: "r"(a), "l"(gmem_src));
}
#define CP_COMMIT() asm volatile("cp.async.commit_group;" ::)
#define CP_WAIT1()  asm volatile("cp.async.wait_group 1;" ::)
#define CP_WAIT0()  asm volatile("cp.async.wait_group 0;" ::)

__device__ __forceinline__ float fast_exp2(float x) {
    float r;
    asm("ex2.approx.f32 %0, %1;" : "=f"(r) : "f"(x));
    return r;
}

// ---------------- K0: C = o_w^T @ head_w^T  (blocks 0,1)  +  E16 = embed @ head_w^T (block 2)
__global__ __launch_bounds__(256) void k_prep_cn(const float* __restrict__ o_w,
                                                 const float* __restrict__ head_w,
                                                 const float* __restrict__ embed) {
    int tid = threadIdx.x;
    if (blockIdx.x < 2) {
        int d = blockIdx.x * 256 + tid;
        float acc[16];
        #pragma unroll
        for (int v = 0; v < 16; ++v) acc[v] = 0.f;
        #pragma unroll 4
        for (int e = 0; e < DMODEL; ++e) {
            float ow = o_w[(size_t)e * DMODEL + d];
            #pragma unroll
            for (int v = 0; v < 16; ++v)
                acc[v] += ow * __ldg(head_w + (size_t)v * DMODEL + e);
        }
        #pragma unroll
        for (int v = 0; v < 16; ++v)
            g_C[d * NVOC + v] = acc[v];
    } else {
        int w = tid >> 4, v = tid & 15;
        float acc = 0.f;
        #pragma unroll 8
        for (int d = 0; d < DMODEL; ++d)
            acc += embed[(size_t)w * DMODEL + d] * head_w[(size_t)v * DMODEL + d];
        g_E16[w * NVOC + v] = acc;
    }
}

// ---------------- K0b: pre-split w1/w2 into bf16 planes ----------------
__global__ __launch_bounds__(256) void k_prep_w(const float* __restrict__ w1,
                                                const float* __restrict__ w2) {
    int i = blockIdx.x * blockDim.x + threadIdx.x;
    if (i >= NP * 2048) return;
    unsigned* wp = (unsigned*)g_wplanes;
    float2 a = ((const float2*)w1)[i];
    unsigned h, l;
    split2(a.x, a.y, h, l);
    wp[0 * NP * 2048 + i] = h;
    wp[1 * NP * 2048 + i] = l;
    float2 b = ((const float2*)w2)[i];
    split2(b.x, b.y, h, l);
    wp[2 * NP * 2048 + i] = h;
    wp[3 * NP * 2048 + i] = l;
}

// ---------------- K1: embedding + layernorm ----------------
__global__ __launch_bounds__(128) void k_embed_ln(
    const int* __restrict__ ids, const float* __restrict__ embed,
    const float* __restrict__ lng, const float* __restrict__ lnb) {
    int t = blockIdx.x;
    int tid = threadIdx.x;
    const float4* row = (const float4*)(embed + (size_t)ids[t] * DMODEL);
    float4 xv = row[tid];
    float s  = xv.x + xv.y + xv.z + xv.w;
    float s2 = xv.x*xv.x + xv.y*xv.y + xv.z*xv.z + xv.w*xv.w;
    #pragma unroll
    for (int o = 16; o; o >>= 1) {
        s  += __shfl_xor_sync(0xffffffffu, s, o);
        s2 += __shfl_xor_sync(0xffffffffu, s2, o);
    }
    __shared__ float sh[8];
    int w = tid >> 5;
    if ((tid & 31) == 0) { sh[w] = s; sh[4 + w] = s2; }
    __syncthreads();
    s  = sh[0] + sh[1] + sh[2] + sh[3];
    s2 = sh[4] + sh[5] + sh[6] + sh[7];
    float mu  = s * (1.0f / DMODEL);
    float var = s2 * (1.0f / DMODEL) - mu * mu;
    float inv = rsqrtf(var + 1e-5f);
    float4 gv = ((const float4*)lng)[tid];
    float4 bv = ((const float4*)lnb)[tid];
    float4 hv;
    hv.x = (xv.x - mu) * inv * gv.x + bv.x;
    hv.y = (xv.y - mu) * inv * gv.y + bv.y;
    hv.z = (xv.z - mu) * inv * gv.z + bv.z;
    hv.w = (xv.w - mu) * inv * gv.w + bv.w;
    ((float4*)(g_x + (size_t)t * DMODEL))[tid] = xv;
    ((float4*)(g_h + (size_t)t * DMODEL))[tid] = hv;
}

// ---------------- K2: compose via bf16 two-plane mma ----------------
// 256 threads = 8 warps (4 row-groups x 2 n-halves). 64 rows/block.
// 3-phase cp.async pipeline: W2(p) fill overlaps GEMM1(p); W1(p+1) overlaps GEMM2(p).
__global__ __launch_bounds__(256, 2) void k_compose(
    const float* __restrict__ pq, const float* __restrict__ gq,
    const float* __restrict__ pk, const float* __restrict__ gk,
    const float* __restrict__ pv, const float* __restrict__ gv) {
    extern __shared__ __align__(16) unsigned short smc[];
    unsigned short* Xh  = smc;               // 64 x 72
    unsigned short* Xl  = Xh  + PLH;
    unsigned short* W1h = Xl  + PLH;
    unsigned short* W1l = W1h + PLH;
    unsigned short* W2h = W1l + PLH;
    unsigned short* W2l = W2h + PLH;
    unsigned short* Sh  = W2l + PLH;
    unsigned short* Sl  = Sh  + PLH;
    float* WG = (float*)(Sl + PLH);          // 3 x 64 x 16

    const int tid = threadIdx.x, warp = tid >> 5, lane = tid & 31;
    const int g = lane >> 2, tg = lane & 3;
    const int mi0 = (lane >> 3) & 1;
    const int mi1 = lane >> 4;
    const int r8 = lane & 7;
    const int wy = warp >> 1, wx = warp & 1;
    const int wr0 = wy * 16, nc0 = wx * 32;
    const int row0 = blockIdx.x * 64;

    unsigned* Xhw = (unsigned*)Xh; unsigned* Xlw = (unsigned*)Xl;
    unsigned* Shw = (unsigned*)Sh; unsigned* Slw = (unsigned*)Sl;

    auto load_w1 = [&](int p) {
        #pragma unroll
        for (int i = tid; i < 1024; i += 256) {
            int plane = i >> 9, j = i & 511;
            int r = j >> 3, c = j & 7;
            cpa16((plane ? W1l : W1h) + r * STR + c * 8,
                  g_wplanes + (size_t)(plane * NP + p) * 4096 + r * 64 + c * 8);
        }
        CP_COMMIT();
    };
    auto load_w2 = [&](int p) {
        #pragma unroll
        for (int i = tid; i < 1024; i += 256) {
            int plane = i >> 9, j = i & 511;
            int r = j >> 3, c = j & 7;
            cpa16((plane ? W2l : W2h) + r * STR + c * 8,
                  g_wplanes + (size_t)((2 + plane) * NP + p) * 4096 + r * 64 + c * 8);
        }
        CP_COMMIT();
    };

    load_w1(0);
    load_w2(0);

    // fill X planes
    #pragma unroll
    for (int i = tid; i < 64 * 16; i += 256) {
        int r = i >> 4, c = i & 15;
        float4 v = ((const float4*)(g_h + (size_t)(row0 + r) * 64))[c];
        unsigned h0, l0, h1, l1;
        split2(v.x, v.y, h0, l0);
        split2(v.z, v.w, h1, l1);
        Xhw[r * WSTR + 2 * c] = h0; Xhw[r * WSTR + 2 * c + 1] = h1;
        Xlw[r * WSTR + 2 * c] = l0; Xlw[r * WSTR + 2 * c + 1] = l1;
    }

    // gate weights
    for (int i = tid; i < 64 * 16; i += 256) {
        int r = i >> 4, p = i & 15;
        const float* xr = g_h + (size_t)(row0 + r) * 64;
        float dq = 0.f, dk = 0.f, dv = 0.f;
        #pragma unroll 8
        for (int d = 0; d < 64; ++d) {
            float xv = __ldg(xr + d);
            dq += xv * pq[p * 64 + d];
            dk += xv * pk[p * 64 + d];
            dv += xv * pv[p * 64 + d];
        }
        float lq = dq * 0.125f - gq[p];
        float lk = dk * 0.125f - gk[p];
        float lv = dv * 0.125f - gv[p];
        WG[(0 * 64 + r) * 16 + p] = lq > 1e-6f ? lq : 0.f;
        WG[(1 * 64 + r) * 16 + p] = lk > 1e-6f ? lk : 0.f;
        WG[(2 * 64 + r) * 16 + p] = lv > 1e-6f ? lv : 0.f;
    }

    float aq[16], ak[16], av[16];
    #pragma unroll
    for (int i = 0; i < 16; ++i) { aq[i] = 0.f; ak[i] = 0.f; av[i] = 0.f; }

    const float LOG2E = 1.44269504f;

    for (int p = 0; p < NP; ++p) {
        CP_WAIT1();        // W1(p) complete; W2(p) may still be in flight
        __syncthreads();

        // GEMM1: H = X @ W1^T  (warp: 16 rows x 32 cols); A-frags via ldmatrix
        float hb[16];
        #pragma unroll
        for (int i = 0; i < 16; ++i) hb[i] = 0.f;
        #pragma unroll
        for (int ks = 0; ks < 4; ++ks) {
            unsigned ah[4], al[4];
            int aoff = (wr0 + mi0 * 8 + r8) * STR + ks * 16 + mi1 * 8;
            ldm_x4(ah, Xh + aoff);
            ldm_x4(al, Xl + aoff);
            #pragma unroll
            for (int np = 0; np < 2; ++np) {
                int roff = (nc0 + np * 16 + mi1 * 8 + r8) * STR + ks * 16 + mi0 * 8;
                unsigned bh[4], bl[4];
                ldm_x4(bh, W1h + roff);
                ldm_x4(bl, W1l + roff);
                mma3(&hb[(np * 2) * 4],     ah, al, bh[0], bh[1], bl[0], bl[1]);
                mma3(&hb[(np * 2 + 1) * 4], ah, al, bh[2], bh[3], bl[2], bl[3]);
            }
        }
        // silu -> S planes
        #pragma unroll
        for (int nt = 0; nt < 4; ++nt) {
            #pragma unroll
            for (int j = 0; j < 4; ++j) {
                float h = hb[nt * 4 + j];
                hb[nt * 4 + j] = h / (1.f + fast_exp2(-h * LOG2E));
            }
            unsigned h0, l0;
            split2(hb[nt * 4 + 0], hb[nt * 4 + 1], h0, l0);
            Shw[(wr0 + g) * WSTR + nc0 / 2 + 4 * nt + tg] = h0;
            Slw[(wr0 + g) * WSTR + nc0 / 2 + 4 * nt + tg] = l0;
            split2(hb[nt * 4 + 2], hb[nt * 4 + 3], h0, l0);
            Shw[(wr0 + g + 8) * WSTR + nc0 / 2 + 4 * nt + tg] = h0;
            Slw[(wr0 + g + 8) * WSTR + nc0 / 2 + 4 * nt + tg] = l0;
        }
        CP_WAIT0();        // W2(p) complete
        __syncthreads();   // S visible, W2 visible, W1 free
        if (p + 1 < NP) load_w1(p + 1);   // overlaps GEMM2

        // GEMM2: out = silu(H) @ W2^T; A-frags via ldmatrix
        float ob[16];
        #pragma unroll
        for (int i = 0; i < 16; ++i) ob[i] = 0.f;
        #pragma unroll
        for (int ks = 0; ks < 4; ++ks) {
            unsigned ah[4], al[4];
            int aoff = (wr0 + mi0 * 8 + r8) * STR + ks * 16 + mi1 * 8;
            ldm_x4(ah, Sh + aoff);
            ldm_x4(al, Sl + aoff);
            #pragma unroll
            for (int np = 0; np < 2; ++np) {
                int roff = (nc0 + np * 16 + mi1 * 8 + r8) * STR + ks * 16 + mi0 * 8;
                unsigned bh[4], bl[4];
                ldm_x4(bh, W2h + roff);
                ldm_x4(bl, W2l + roff);
                mma3(&ob[(np * 2) * 4],     ah, al, bh[0], bh[1], bl[0], bl[1]);
                mma3(&ob[(np * 2 + 1) * 4], ah, al, bh[2], bh[3], bl[2], bl[3]);
            }
        }
        // gated accumulate
        float wq0 = WG[(0 * 64 + wr0 + g)     * 16 + p];
        float wq1 = WG[(0 * 64 + wr0 + g + 8) * 16 + p];
        float wk0 = WG[(1 * 64 + wr0 + g)     * 16 + p];
        float wk1 = WG[(1 * 64 + wr0 + g + 8) * 16 + p];
        float wv0 = WG[(2 * 64 + wr0 + g)     * 16 + p];
        float wv1 = WG[(2 * 64 + wr0 + g + 8) * 16 + p];
        #pragma unroll
        for (int nt = 0; nt < 4; ++nt) {
            aq[nt*4+0] += wq0 * ob[nt*4+0]; aq[nt*4+1] += wq0 * ob[nt*4+1];
            aq[nt*4+2] += wq1 * ob[nt*4+2]; aq[nt*4+3] += wq1 * ob[nt*4+3];
            ak[nt*4+0] += wk0 * ob[nt*4+0]; ak[nt*4+1] += wk0 * ob[nt*4+1];
            ak[nt*4+2] += wk1 * ob[nt*4+2]; ak[nt*4+3] += wk1 * ob[nt*4+3];
            av[nt*4+0] += wv0 * ob[nt*4+0]; av[nt*4+1] += wv0 * ob[nt*4+1];
            av[nt*4+2] += wv1 * ob[nt*4+2]; av[nt*4+3] += wv1 * ob[nt*4+3];
        }
        __syncthreads();   // W2/S free
        if (p + 1 < NP) load_w2(p + 1);   // overlaps next GEMM1
    }

    // write q,k,v to [bh][t][64]
    int r_lo = row0 + wr0 + g;
    int r_hi = r_lo + 8;
    int tok_lo = r_lo >> 3, h_lo = r_lo & 7;
    int tok_hi = r_hi >> 3, h_hi = r_hi & 7;
    int b_lo = tok_lo >> 11, t_lo = tok_lo & 2047;
    int b_hi = tok_hi >> 11, t_hi = tok_hi & 2047;
    size_t base_lo = ((size_t)(b_lo * 8 + h_lo) * NT + t_lo) * 64;
    size_t base_hi = ((size_t)(b_hi * 8 + h_hi) * NT + t_hi) * 64;
    #pragma unroll
    for (int nt = 0; nt < 4; ++nt) {
        int col = nc0 + nt * 8 + 2 * tg;
        *(float2*)&g_q[base_lo + col] = make_float2(aq[nt*4+0], aq[nt*4+1]);
        *(float2*)&g_q[base_hi + col] = make_float2(aq[nt*4+2], aq[nt*4+3]);
        *(float2*)&g_k[base_lo + col] = make_float2(ak[nt*4+0], ak[nt*4+1]);
        *(float2*)&g_k[base_hi + col] = make_float2(ak[nt*4+2], ak[nt*4+3]);
        *(float2*)&g_v[base_lo + col] = make_float2(av[nt*4+0], av[nt*4+1]);
        *(float2*)&g_v[base_hi + col] = make_float2(av[nt*4+2], av[nt*4+3]);
    }
}

// ---------------- K3: flash attention via bf16 two-plane mma ----------------
// 128 threads = 4 warps x 16 q rows; 64-row Q tile, 64-row K tile.
__global__ __launch_bounds__(128) void k_attn() {
    extern __shared__ __align__(16) unsigned short sma[];
    unsigned short* Kh = sma;
    unsigned short* Kl = Kh + PLH;
    unsigned short* Vh = Kl + PLH;
    unsigned short* Vl = Vh + PLH;
    unsigned* Khw = (unsigned*)Kh; unsigned* Klw = (unsigned*)Kl;
    unsigned* Vhw = (unsigned*)Vh; unsigned* Vlw = (unsigned*)Vl;

    const int tid = threadIdx.x, warp = tid >> 5, lane = tid & 31;
    const int g = lane >> 2, tg = lane & 3;
    const int mi0 = (lane >> 3) & 1;
    const int mi1 = lane >> 4;
    const int r8 = lane & 7;
    const int qtile = 31 - blockIdx.x;
    const int qt0 = qtile * 64;
    const int bh = blockIdx.y;
    const int b = bh >> 3, h = bh & 7;
    const float* qbase = g_q + (size_t)bh * NT * 64;
    const float* kbase = g_k + (size_t)bh * NT * 64;
    const float* vbase = g_v + (size_t)bh * NT * 64;
    const int wr0 = warp * 16;

    unsigned Qh[4][4], Ql[4][4];
    {
        const float* qr0 = qbase + (size_t)(qt0 + wr0 + g) * 64 + 2 * tg;
        const float* qr1 = qbase + (size_t)(qt0 + wr0 + g + 8) * 64 + 2 * tg;
        #pragma unroll
        for (int ks = 0; ks < 4; ++ks) {
            float2 v;
            v = *(const float2*)(qr0 + 16 * ks);     split2(v.x, v.y, Qh[ks][0], Ql[ks][0]);
            v = *(const float2*)(qr1 + 16 * ks);     split2(v.x, v.y, Qh[ks][1], Ql[ks][1]);
            v = *(const float2*)(qr0 + 16 * ks + 8); split2(v.x, v.y, Qh[ks][2], Ql[ks][2]);
            v = *(const float2*)(qr1 + 16 * ks + 8); split2(v.x, v.y, Qh[ks][3], Ql[ks][3]);
        }
    }

    float O[32];
    #pragma unroll
    for (int i = 0; i < 32; ++i) O[i] = 0.f;
    float m2[2] = {-1e30f, -1e30f};
    float l2[2] = {0.f, 0.f};
    const float sc = 0.125f * 1.44269504f;

    for (int kt = 0; kt <= qtile; ++kt) {
        __syncthreads();
        #pragma unroll
        for (int i = tid; i < 64 * 16; i += 128) {
            int r = i >> 4, c = i & 15;
            size_t base = (size_t)(kt * 64 + r) * 64 + 4 * c;
            float4 kv = *(const float4*)(kbase + base);
            float4 vv = *(const float4*)(vbase + base);
            unsigned h0, l0, h1, l1;
            split2(kv.x, kv.y, h0, l0); split2(kv.z, kv.w, h1, l1);
            Khw[r * WSTR + 2 * c] = h0; Khw[r * WSTR + 2 * c + 1] = h1;
            Klw[r * WSTR + 2 * c] = l0; Klw[r * WSTR + 2 * c + 1] = l1;
            split2(vv.x, vv.y, h0, l0); split2(vv.z, vv.w, h1, l1);
            Vhw[r * WSTR + 2 * c] = h0; Vhw[r * WSTR + 2 * c + 1] = h1;
            Vlw[r * WSTR + 2 * c] = l0; Vlw[r * WSTR + 2 * c + 1] = l1;
        }
        __syncthreads();

        const bool diag = (kt == qtile);
        const int npmax = diag ? warp : 3;

        float s[32];
        #pragma unroll
        for (int i = 0; i < 32; ++i) s[i] = 0.f;
        #pragma unroll
        for (int ks = 0; ks < 4; ++ks) {
            for (int np = 0; np <= npmax; ++np) {
                int roff = (np * 16 + mi1 * 8 + r8) * STR + ks * 16 + mi0 * 8;
                unsigned bh4[4], bl4[4];
                ldm_x4(bh4, Kh + roff);
                ldm_x4(bl4, Kl + roff);
                mma3(&s[(np * 2) * 4],     Qh[ks], Ql[ks], bh4[0], bh4[1], bl4[0], bl4[1]);
                mma3(&s[(np * 2 + 1) * 4], Qh[ks], Ql[ks], bh4[2], bh4[3], bl4[2], bl4[3]);
            }
        }
        #pragma unroll
        for (int nt = 0; nt < 8; ++nt)
            #pragma unroll
            for (int j = 0; j < 4; ++j) {
                int rr = qt0 + wr0 + g + (j >> 1) * 8;
                int cc = kt * 64 + nt * 8 + 2 * tg + (j & 1);
                float v = s[nt * 4 + j] * sc;
                if (diag && cc > rr) v = -1e30f;
                s[nt * 4 + j] = v;
            }
        #pragma unroll
        for (int h2 = 0; h2 < 2; ++h2) {
            float mx = -1e30f;
            #pragma unroll
            for (int nt = 0; nt < 8; ++nt) {
                mx = fmaxf(mx, s[nt * 4 + h2 * 2 + 0]);
                mx = fmaxf(mx, s[nt * 4 + h2 * 2 + 1]);
            }
            mx = fmaxf(mx, __shfl_xor_sync(0xffffffffu, mx, 1));
            mx = fmaxf(mx, __shfl_xor_sync(0xffffffffu, mx, 2));
            float mn = fmaxf(m2[h2], mx);
            float alpha = fast_exp2(m2[h2] - mn);
            m2[h2] = mn;
            float rs = 0.f;
            #pragma unroll
            for (int nt = 0; nt < 8; ++nt) {
                float p0 = fast_exp2(s[nt * 4 + h2 * 2 + 0] - mn);
                float p1 = fast_exp2(s[nt * 4 + h2 * 2 + 1] - mn);
                s[nt * 4 + h2 * 2 + 0] = p0;
                s[nt * 4 + h2 * 2 + 1] = p1;
                rs += p0 + p1;
            }
            rs += __shfl_xor_sync(0xffffffffu, rs, 1);
            rs += __shfl_xor_sync(0xffffffffu, rs, 2);
            l2[h2] = l2[h2] * alpha + rs;
            #pragma unroll
            for (int nt = 0; nt < 8; ++nt) {
                O[nt * 4 + h2 * 2 + 0] *= alpha;
                O[nt * 4 + h2 * 2 + 1] *= alpha;
            }
        }
        const int ksmax = diag ? warp : 3;
        #pragma unroll
        for (int ks = 0; ks < 4; ++ks) {
            if (ks > ksmax) break;
            unsigned pah[4], pal[4];
            split2(s[8 * ks + 0], s[8 * ks + 1], pah[0], pal[0]);
            split2(s[8 * ks + 2], s[8 * ks + 3], pah[1], pal[1]);
            split2(s[8 * ks + 4], s[8 * ks + 5], pah[2], pal[2]);
            split2(s[8 * ks + 6], s[8 * ks + 7], pah[3], pal[3]);
            #pragma unroll
            for (int np = 0; np < 4; ++np) {
                int roff = (ks * 16 + mi0 * 8 + r8) * STR + np * 16 + mi1 * 8;
                unsigned vh4[4], vl4[4];
                ldm_x4_t(vh4, Vh + roff);
                ldm_x4_t(vl4, Vl + roff);
                mma3(&O[(np * 2) * 4],     pah, pal, vh4[0], vh4[1], vl4[0], vl4[1]);
                mma3(&O[(np * 2 + 1) * 4], pah, pal, vh4[2], vh4[3], vl4[2], vl4[3]);
            }
        }
    }

    float inv0 = 1.f / l2[0];
    float inv1 = 1.f / l2[1];
    int r_lo = qt0 + wr0 + g;
    int r_hi = r_lo + 8;
    size_t base_lo = ((size_t)(b * NT + r_lo) * 8 + h) * 64;
    size_t base_hi = ((size_t)(b * NT + r_hi) * 8 + h) * 64;
    #pragma unroll
    for (int nt = 0; nt < 8; ++nt) {
        int col = nt * 8 + 2 * tg;
        *(float2*)&g_attn[base_lo + col] =
            make_float2(O[nt*4+0] * inv0, O[nt*4+1] * inv0);
        *(float2*)&g_attn[base_hi + col] =
            make_float2(O[nt*4+2] * inv1, O[nt*4+3] * inv1);
    }
}

// ---------------- K4: logits[t] = E16[ids[t]] + attn_row @ C ----------------
// 8 tokens/block; C in smem (17-stride, conflict-free); shfl reduction.
__global__ __launch_bounds__(256) void k_final(const int* __restrict__ ids,
                                               float* __restrict__ out) {
    __shared__ float Cs[DMODEL * 17];   // 34816 B
    __shared__ float xa[DMODEL];
    int tid = threadIdx.x;
    for (int i = tid; i < DMODEL * NVOC; i += 256) {
        int d = i >> 4, v = i & 15;
        Cs[d * 17 + v] = g_C[i];
    }
    int v = tid >> 4, ch = tid & 15;
    int t0 = blockIdx.x * 8;
    __syncthreads();
    for (int tt = 0; tt < 8; ++tt) {
        int t = t0 + tt;
        for (int i = tid; i < DMODEL; i += 256)
            xa[i] = g_attn[(size_t)t * DMODEL + i];
        __syncthreads();
        float acc = 0.f;
        #pragma unroll
        for (int j = 0; j < 32; ++j) {
            int d = j * 16 + ch;
            acc += xa[d] * Cs[d * 17 + v];
        }
        acc += __shfl_xor_sync(0xffffffffu, acc, 1);
        acc += __shfl_xor_sync(0xffffffffu, acc, 2);
        acc += __shfl_xor_sync(0xffffffffu, acc, 4);
        acc += __shfl_xor_sync(0xffffffffu, acc, 8);
        if (ch == 0)
            out[(size_t)t * NVOC + v] = acc + g_E16[ids[t] * NVOC + v];
        __syncthreads();
    }
}

// ---------------- launch ----------------
extern "C" void kernel_launch(void* const* d_in, const int* in_sizes, int n_in,
                              void* d_out, int out_size) {
    const int*   ids    = (const int*)d_in[0];
    const float* embed  = (const float*)d_in[1];
    const float* ln_g   = (const float*)d_in[2];
    const float* ln_b   = (const float*)d_in[3];
    const float* pq     = (const float*)d_in[4];
    const float* gq     = (const float*)d_in[5];
    const float* pk     = (const float*)d_in[6];
    const float* gk     = (const float*)d_in[7];
    const float* pv     = (const float*)d_in[8];
    const float* gv     = (const float*)d_in[9];
    const float* w1     = (const float*)d_in[10];
    const float* w2     = (const float*)d_in[11];
    const float* o_w    = (const float*)d_in[12];
    const float* head_w = (const float*)d_in[13];
    float* out = (float*)d_out;

    const int smem_compose = 8 * PLH * 2 + 3 * 64 * 16 * 4;  // 86016
    const int smem_attn    = 4 * PLH * 2;                    // 36864
    cudaFuncSetAttribute(k_compose, cudaFuncAttributeMaxDynamicSharedMemorySize, smem_compose);
    cudaFuncSetAttribute(k_attn,    cudaFuncAttributeMaxDynamicSharedMemorySize, smem_attn);

    k_prep_cn<<<3, 256>>>(o_w, head_w, embed);
    k_prep_w<<<NP * 2048 / 256, 256>>>(w1, w2);
    k_embed_ln<<<NTOK, 128>>>(ids, embed, ln_g, ln_b);
    k_compose<<<NTH / 64, 256, smem_compose>>>(pq, gq, pk, gk, pv, gv);
    dim3 ag(NT / 64, NB * NHEAD);
    k_attn<<<ag, 128, smem_attn>>>();
    k_final<<<NTOK / 8, 256>>>(ids, out);
}

// round 16
// speedup vs baseline: 1.2699x; 1.2590x over previous
#include <cuda_runtime.h>

#define NHEAD 8
#define HD 64
#define DMODEL 512
#define NP 16
#define NB 2
#define NT 2048
#define NVOC 16
#define NTOK (NB*NT)        // 4096
#define NTH (NTOK*NHEAD)    // 32768

#define STR 72    // bf16 halfs per smem plane row
#define WSTR 36   // 32-bit words per row
#define PLH (64*STR)

// ---------------- scratch ----------------
__device__ float g_x[NTOK*DMODEL];
__device__ float g_h[NTOK*DMODEL];
__device__ float g_q[NTH*HD];     // [bh][t][64]
__device__ float g_k[NTH*HD];
__device__ float g_v[NTH*HD];
__device__ float g_attn[NTH*HD];  // [token][head][64]
__device__ float g_C[DMODEL*NVOC];
__device__ float g_E16[NVOC*NVOC];   // embed @ head_w^T
// weight planes: [plane(W1h,W1l,W2h,W2l)][expert][64][64] bf16
__device__ unsigned short g_wplanes[4*NP*4096];

__device__ __forceinline__ void split2(float x0, float x1, unsigned &h, unsigned &l) {
    asm("cvt.rn.bf16x2.f32 %0, %1, %2;" : "=r"(h) : "f"(x1), "f"(x0));
    float h0 = __uint_as_float(h << 16);
    float h1 = __uint_as_float(h & 0xffff0000u);
    asm("cvt.rn.bf16x2.f32 %0, %1, %2;" : "=r"(l) : "f"(x1 - h1), "f"(x0 - h0));
}

__device__ __forceinline__ void mma_bf16(float* c, unsigned a0, unsigned a1,
                                         unsigned a2, unsigned a3,
                                         unsigned b0, unsigned b1) {
    asm volatile(
        "mma.sync.aligned.m16n8k16.row.col.f32.bf16.bf16.f32 "
        "{%0,%1,%2,%3}, {%4,%5,%6,%7}, {%8,%9}, {%0,%1,%2,%3};\n"
        : "+f"(c[0]), "+f"(c[1]), "+f"(c[2]), "+f"(c[3])
        : "r"(a0), "r"(a1), "r"(a2), "r"(a3), "r"(b0), "r"(b1));
}
__device__ __forceinline__ void mma3(float* c, const unsigned* ah, const unsigned* al,
                                     unsigned b0h, unsigned b1h,
                                     unsigned b0l, unsigned b1l) {
    mma_bf16(c, al[0], al[1], al[2], al[3], b0h, b1h);
    mma_bf16(c, ah[0], ah[1], ah[2], ah[3], b0l, b1l);
    mma_bf16(c, ah[0], ah[1], ah[2], ah[3], b0h, b1h);
}
__device__ __forceinline__ void ldm_x4(unsigned* r, const unsigned short* p) {
    unsigned a = (unsigned)__cvta_generic_to_shared(p);
    asm volatile("ldmatrix.sync.aligned.m8n8.x4.shared.b16 {%0,%1,%2,%3}, [%4];"
                 : "=r"(r[0]), "=r"(r[1]), "=r"(r[2]), "=r"(r[3]) : "r"(a));
}
__device__ __forceinline__ void ldm_x4_t(unsigned* r, const unsigned short* p) {
    unsigned a = (unsigned)__cvta_generic_to_shared(p);
    asm volatile("ldmatrix.sync.aligned.m8n8.x4.trans.shared.b16 {%0,%1,%2,%3}, [%4];"
                 : "=r"(r[0]), "=r"(r[1]), "=r"(r[2]), "=r"(r[3]) : "r"(a));
}
__device__ __forceinline__ void cpa16(const void* smem_dst, const void* gmem_src) {
    unsigned a = (unsigned)__cvta_generic_to_shared(smem_dst);
    asm volatile("cp.async.cg.shared.global [%0], [%1], 16;" :: "r"(a), "l"(gmem_src));
}
#define CP_COMMIT() asm volatile("cp.async.commit_group;" ::)
#define CP_WAIT1()  asm volatile("cp.async.wait_group 1;" ::)
#define CP_WAIT0()  asm volatile("cp.async.wait_group 0;" ::)

__device__ __forceinline__ float fast_exp2(float x) {
    float r;
    asm("ex2.approx.f32 %0, %1;" : "=f"(r) : "f"(x));
    return r;
}

// ---------------- K0: C = o_w^T @ head_w^T  (blocks 0,1)  +  E16 = embed @ head_w^T (block 2)
__global__ __launch_bounds__(256) void k_prep_cn(const float* __restrict__ o_w,
                                                 const float* __restrict__ head_w,
                                                 const float* __restrict__ embed) {
    int tid = threadIdx.x;
    if (blockIdx.x < 2) {
        int d = blockIdx.x * 256 + tid;
        float acc[16];
        #pragma unroll
        for (int v = 0; v < 16; ++v) acc[v] = 0.f;
        #pragma unroll 4
        for (int e = 0; e < DMODEL; ++e) {
            float ow = o_w[(size_t)e * DMODEL + d];
            #pragma unroll
            for (int v = 0; v < 16; ++v)
                acc[v] += ow * __ldg(head_w + (size_t)v * DMODEL + e);
        }
        #pragma unroll
        for (int v = 0; v < 16; ++v)
            g_C[d * NVOC + v] = acc[v];
    } else {
        int w = tid >> 4, v = tid & 15;
        float acc = 0.f;
        #pragma unroll 8
        for (int d = 0; d < DMODEL; ++d)
            acc += embed[(size_t)w * DMODEL + d] * head_w[(size_t)v * DMODEL + d];
        g_E16[w * NVOC + v] = acc;
    }
}

// ---------------- K0b: pre-split w1/w2 into bf16 planes ----------------
__global__ __launch_bounds__(256) void k_prep_w(const float* __restrict__ w1,
                                                const float* __restrict__ w2) {
    int i = blockIdx.x * blockDim.x + threadIdx.x;
    if (i >= NP * 2048) return;
    unsigned* wp = (unsigned*)g_wplanes;
    float2 a = ((const float2*)w1)[i];
    unsigned h, l;
    split2(a.x, a.y, h, l);
    wp[0 * NP * 2048 + i] = h;
    wp[1 * NP * 2048 + i] = l;
    float2 b = ((const float2*)w2)[i];
    split2(b.x, b.y, h, l);
    wp[2 * NP * 2048 + i] = h;
    wp[3 * NP * 2048 + i] = l;
}

// ---------------- K1: embedding + layernorm ----------------
__global__ __launch_bounds__(128) void k_embed_ln(
    const int* __restrict__ ids, const float* __restrict__ embed,
    const float* __restrict__ lng, const float* __restrict__ lnb) {
    int t = blockIdx.x;
    int tid = threadIdx.x;
    const float4* row = (const float4*)(embed + (size_t)ids[t] * DMODEL);
    float4 xv = row[tid];
    float s  = xv.x + xv.y + xv.z + xv.w;
    float s2 = xv.x*xv.x + xv.y*xv.y + xv.z*xv.z + xv.w*xv.w;
    #pragma unroll
    for (int o = 16; o; o >>= 1) {
        s  += __shfl_xor_sync(0xffffffffu, s, o);
        s2 += __shfl_xor_sync(0xffffffffu, s2, o);
    }
    __shared__ float sh[8];
    int w = tid >> 5;
    if ((tid & 31) == 0) { sh[w] = s; sh[4 + w] = s2; }
    __syncthreads();
    s  = sh[0] + sh[1] + sh[2] + sh[3];
    s2 = sh[4] + sh[5] + sh[6] + sh[7];
    float mu  = s * (1.0f / DMODEL);
    float var = s2 * (1.0f / DMODEL) - mu * mu;
    float inv = rsqrtf(var + 1e-5f);
    float4 gv = ((const float4*)lng)[tid];
    float4 bv = ((const float4*)lnb)[tid];
    float4 hv;
    hv.x = (xv.x - mu) * inv * gv.x + bv.x;
    hv.y = (xv.y - mu) * inv * gv.y + bv.y;
    hv.z = (xv.z - mu) * inv * gv.z + bv.z;
    hv.w = (xv.w - mu) * inv * gv.w + bv.w;
    ((float4*)(g_x + (size_t)t * DMODEL))[tid] = xv;
    ((float4*)(g_h + (size_t)t * DMODEL))[tid] = hv;
}

// ---------------- K2: compose via bf16 two-plane mma ----------------
// 256 threads = 8 warps (4 row-groups x 2 n-halves). 64 rows/block.
// 3-phase cp.async pipeline: W2(p) fill overlaps GEMM1(p); W1(p+1) overlaps GEMM2(p).
__global__ __launch_bounds__(256, 2) void k_compose(
    const float* __restrict__ pq, const float* __restrict__ gq,
    const float* __restrict__ pk, const float* __restrict__ gk,
    const float* __restrict__ pv, const float* __restrict__ gv) {
    extern __shared__ __align__(16) unsigned short smc[];
    unsigned short* Xh  = smc;               // 64 x 72
    unsigned short* Xl  = Xh  + PLH;
    unsigned short* W1h = Xl  + PLH;
    unsigned short* W1l = W1h + PLH;
    unsigned short* W2h = W1l + PLH;
    unsigned short* W2l = W2h + PLH;
    unsigned short* Sh  = W2l + PLH;
    unsigned short* Sl  = Sh  + PLH;
    float* WG = (float*)(Sl + PLH);          // 3 x 64 x 16

    const int tid = threadIdx.x, warp = tid >> 5, lane = tid & 31;
    const int g = lane >> 2, tg = lane & 3;
    const int mi0 = (lane >> 3) & 1;
    const int mi1 = lane >> 4;
    const int r8 = lane & 7;
    const int wy = warp >> 1, wx = warp & 1;
    const int wr0 = wy * 16, nc0 = wx * 32;
    const int row0 = blockIdx.x * 64;

    unsigned* Xhw = (unsigned*)Xh; unsigned* Xlw = (unsigned*)Xl;
    unsigned* Shw = (unsigned*)Sh; unsigned* Slw = (unsigned*)Sl;

    auto load_w1 = [&](int p) {
        #pragma unroll
        for (int i = tid; i < 1024; i += 256) {
            int plane = i >> 9, j = i & 511;
            int r = j >> 3, c = j & 7;
            cpa16((plane ? W1l : W1h) + r * STR + c * 8,
                  g_wplanes + (size_t)(plane * NP + p) * 4096 + r * 64 + c * 8);
        }
        CP_COMMIT();
    };
    auto load_w2 = [&](int p) {
        #pragma unroll
        for (int i = tid; i < 1024; i += 256) {
            int plane = i >> 9, j = i & 511;
            int r = j >> 3, c = j & 7;
            cpa16((plane ? W2l : W2h) + r * STR + c * 8,
                  g_wplanes + (size_t)((2 + plane) * NP + p) * 4096 + r * 64 + c * 8);
        }
        CP_COMMIT();
    };

    load_w1(0);
    load_w2(0);

    // fill X planes
    #pragma unroll
    for (int i = tid; i < 64 * 16; i += 256) {
        int r = i >> 4, c = i & 15;
        float4 v = ((const float4*)(g_h + (size_t)(row0 + r) * 64))[c];
        unsigned h0, l0, h1, l1;
        split2(v.x, v.y, h0, l0);
        split2(v.z, v.w, h1, l1);
        Xhw[r * WSTR + 2 * c] = h0; Xhw[r * WSTR + 2 * c + 1] = h1;
        Xlw[r * WSTR + 2 * c] = l0; Xlw[r * WSTR + 2 * c + 1] = l1;
    }

    // gate weights
    for (int i = tid; i < 64 * 16; i += 256) {
        int r = i >> 4, p = i & 15;
        const float* xr = g_h + (size_t)(row0 + r) * 64;
        float dq = 0.f, dk = 0.f, dv = 0.f;
        #pragma unroll 8
        for (int d = 0; d < 64; ++d) {
            float xv = __ldg(xr + d);
            dq += xv * pq[p * 64 + d];
            dk += xv * pk[p * 64 + d];
            dv += xv * pv[p * 64 + d];
        }
        float lq = dq * 0.125f - gq[p];
        float lk = dk * 0.125f - gk[p];
        float lv = dv * 0.125f - gv[p];
        WG[(0 * 64 + r) * 16 + p] = lq > 1e-6f ? lq : 0.f;
        WG[(1 * 64 + r) * 16 + p] = lk > 1e-6f ? lk : 0.f;
        WG[(2 * 64 + r) * 16 + p] = lv > 1e-6f ? lv : 0.f;
    }

    float aq[16], ak[16], av[16];
    #pragma unroll
    for (int i = 0; i < 16; ++i) { aq[i] = 0.f; ak[i] = 0.f; av[i] = 0.f; }

    const float LOG2E = 1.44269504f;

    for (int p = 0; p < NP; ++p) {
        CP_WAIT1();        // W1(p) complete; W2(p) may still be in flight
        __syncthreads();

        // GEMM1: H = X @ W1^T  (warp: 16 rows x 32 cols); A-frags via ldmatrix
        float hb[16];
        #pragma unroll
        for (int i = 0; i < 16; ++i) hb[i] = 0.f;
        #pragma unroll
        for (int ks = 0; ks < 4; ++ks) {
            unsigned ah[4], al[4];
            int aoff = (wr0 + mi0 * 8 + r8) * STR + ks * 16 + mi1 * 8;
            ldm_x4(ah, Xh + aoff);
            ldm_x4(al, Xl + aoff);
            #pragma unroll
            for (int np = 0; np < 2; ++np) {
                int roff = (nc0 + np * 16 + mi1 * 8 + r8) * STR + ks * 16 + mi0 * 8;
                unsigned bh[4], bl[4];
                ldm_x4(bh, W1h + roff);
                ldm_x4(bl, W1l + roff);
                mma3(&hb[(np * 2) * 4],     ah, al, bh[0], bh[1], bl[0], bl[1]);
                mma3(&hb[(np * 2 + 1) * 4], ah, al, bh[2], bh[3], bl[2], bl[3]);
            }
        }
        // silu -> S planes
        #pragma unroll
        for (int nt = 0; nt < 4; ++nt) {
            #pragma unroll
            for (int j = 0; j < 4; ++j) {
                float h = hb[nt * 4 + j];
                hb[nt * 4 + j] = h / (1.f + fast_exp2(-h * LOG2E));
            }
            unsigned h0, l0;
            split2(hb[nt * 4 + 0], hb[nt * 4 + 1], h0, l0);
            Shw[(wr0 + g) * WSTR + nc0 / 2 + 4 * nt + tg] = h0;
            Slw[(wr0 + g) * WSTR + nc0 / 2 + 4 * nt + tg] = l0;
            split2(hb[nt * 4 + 2], hb[nt * 4 + 3], h0, l0);
            Shw[(wr0 + g + 8) * WSTR + nc0 / 2 + 4 * nt + tg] = h0;
            Slw[(wr0 + g + 8) * WSTR + nc0 / 2 + 4 * nt + tg] = l0;
        }
        CP_WAIT0();        // W2(p) complete
        __syncthreads();   // S visible, W2 visible, W1 free
        if (p + 1 < NP) load_w1(p + 1);   // overlaps GEMM2

        // GEMM2: out = silu(H) @ W2^T; A-frags via ldmatrix
        float ob[16];
        #pragma unroll
        for (int i = 0; i < 16; ++i) ob[i] = 0.f;
        #pragma unroll
        for (int ks = 0; ks < 4; ++ks) {
            unsigned ah[4], al[4];
            int aoff = (wr0 + mi0 * 8 + r8) * STR + ks * 16 + mi1 * 8;
            ldm_x4(ah, Sh + aoff);
            ldm_x4(al, Sl + aoff);
            #pragma unroll
            for (int np = 0; np < 2; ++np) {
                int roff = (nc0 + np * 16 + mi1 * 8 + r8) * STR + ks * 16 + mi0 * 8;
                unsigned bh[4], bl[4];
                ldm_x4(bh, W2h + roff);
                ldm_x4(bl, W2l + roff);
                mma3(&ob[(np * 2) * 4],     ah, al, bh[0], bh[1], bl[0], bl[1]);
                mma3(&ob[(np * 2 + 1) * 4], ah, al, bh[2], bh[3], bl[2], bl[3]);
            }
        }
        // gated accumulate
        float wq0 = WG[(0 * 64 + wr0 + g)     * 16 + p];
        float wq1 = WG[(0 * 64 + wr0 + g + 8) * 16 + p];
        float wk0 = WG[(1 * 64 + wr0 + g)     * 16 + p];
        float wk1 = WG[(1 * 64 + wr0 + g + 8) * 16 + p];
        float wv0 = WG[(2 * 64 + wr0 + g)     * 16 + p];
        float wv1 = WG[(2 * 64 + wr0 + g + 8) * 16 + p];
        #pragma unroll
        for (int nt = 0; nt < 4; ++nt) {
            aq[nt*4+0] += wq0 * ob[nt*4+0]; aq[nt*4+1] += wq0 * ob[nt*4+1];
            aq[nt*4+2] += wq1 * ob[nt*4+2]; aq[nt*4+3] += wq1 * ob[nt*4+3];
            ak[nt*4+0] += wk0 * ob[nt*4+0]; ak[nt*4+1] += wk0 * ob[nt*4+1];
            ak[nt*4+2] += wk1 * ob[nt*4+2]; ak[nt*4+3] += wk1 * ob[nt*4+3];
            av[nt*4+0] += wv0 * ob[nt*4+0]; av[nt*4+1] += wv0 * ob[nt*4+1];
            av[nt*4+2] += wv1 * ob[nt*4+2]; av[nt*4+3] += wv1 * ob[nt*4+3];
        }
        __syncthreads();   // W2/S free
        if (p + 1 < NP) load_w2(p + 1);   // overlaps next GEMM1
    }

    // write q,k,v to [bh][t][64]
    int r_lo = row0 + wr0 + g;
    int r_hi = r_lo + 8;
    int tok_lo = r_lo >> 3, h_lo = r_lo & 7;
    int tok_hi = r_hi >> 3, h_hi = r_hi & 7;
    int b_lo = tok_lo >> 11, t_lo = tok_lo & 2047;
    int b_hi = tok_hi >> 11, t_hi = tok_hi & 2047;
    size_t base_lo = ((size_t)(b_lo * 8 + h_lo) * NT + t_lo) * 64;
    size_t base_hi = ((size_t)(b_hi * 8 + h_hi) * NT + t_hi) * 64;
    #pragma unroll
    for (int nt = 0; nt < 4; ++nt) {
        int col = nc0 + nt * 8 + 2 * tg;
        *(float2*)&g_q[base_lo + col] = make_float2(aq[nt*4+0], aq[nt*4+1]);
        *(float2*)&g_q[base_hi + col] = make_float2(aq[nt*4+2], aq[nt*4+3]);
        *(float2*)&g_k[base_lo + col] = make_float2(ak[nt*4+0], ak[nt*4+1]);
        *(float2*)&g_k[base_hi + col] = make_float2(ak[nt*4+2], ak[nt*4+3]);
        *(float2*)&g_v[base_lo + col] = make_float2(av[nt*4+0], av[nt*4+1]);
        *(float2*)&g_v[base_hi + col] = make_float2(av[nt*4+2], av[nt*4+3]);
    }
}

// ---------------- K3: flash attention via bf16 two-plane mma ----------------
// 128 threads = 4 warps x 16 q rows; 64-row Q tile, 64-row K tile.
__global__ __launch_bounds__(128) void k_attn() {
    extern __shared__ __align__(16) unsigned short sma[];
    unsigned short* Kh = sma;
    unsigned short* Kl = Kh + PLH;
    unsigned short* Vh = Kl + PLH;
    unsigned short* Vl = Vh + PLH;
    unsigned* Khw = (unsigned*)Kh; unsigned* Klw = (unsigned*)Kl;
    unsigned* Vhw = (unsigned*)Vh; unsigned* Vlw = (unsigned*)Vl;

    const int tid = threadIdx.x, warp = tid >> 5, lane = tid & 31;
    const int g = lane >> 2, tg = lane & 3;
    const int mi0 = (lane >> 3) & 1;
    const int mi1 = lane >> 4;
    const int r8 = lane & 7;
    const int qtile = 31 - blockIdx.x;
    const int qt0 = qtile * 64;
    const int bh = blockIdx.y;
    const int b = bh >> 3, h = bh & 7;
    const float* qbase = g_q + (size_t)bh * NT * 64;
    const float* kbase = g_k + (size_t)bh * NT * 64;
    const float* vbase = g_v + (size_t)bh * NT * 64;
    const int wr0 = warp * 16;

    unsigned Qh[4][4], Ql[4][4];
    {
        const float* qr0 = qbase + (size_t)(qt0 + wr0 + g) * 64 + 2 * tg;
        const float* qr1 = qbase + (size_t)(qt0 + wr0 + g + 8) * 64 + 2 * tg;
        #pragma unroll
        for (int ks = 0; ks < 4; ++ks) {
            float2 v;
            v = *(const float2*)(qr0 + 16 * ks);     split2(v.x, v.y, Qh[ks][0], Ql[ks][0]);
            v = *(const float2*)(qr1 + 16 * ks);     split2(v.x, v.y, Qh[ks][1], Ql[ks][1]);
            v = *(const float2*)(qr0 + 16 * ks + 8); split2(v.x, v.y, Qh[ks][2], Ql[ks][2]);
            v = *(const float2*)(qr1 + 16 * ks + 8); split2(v.x, v.y, Qh[ks][3], Ql[ks][3]);
        }
    }

    float O[32];
    #pragma unroll
    for (int i = 0; i < 32; ++i) O[i] = 0.f;
    float m2[2] = {-1e30f, -1e30f};
    float l2[2] = {0.f, 0.f};
    const float sc = 0.125f * 1.44269504f;

    for (int kt = 0; kt <= qtile; ++kt) {
        __syncthreads();
        #pragma unroll
        for (int i = tid; i < 64 * 16; i += 128) {
            int r = i >> 4, c = i & 15;
            size_t base = (size_t)(kt * 64 + r) * 64 + 4 * c;
            float4 kv = *(const float4*)(kbase + base);
            float4 vv = *(const float4*)(vbase + base);
            unsigned h0, l0, h1, l1;
            split2(kv.x, kv.y, h0, l0); split2(kv.z, kv.w, h1, l1);
            Khw[r * WSTR + 2 * c] = h0; Khw[r * WSTR + 2 * c + 1] = h1;
            Klw[r * WSTR + 2 * c] = l0; Klw[r * WSTR + 2 * c + 1] = l1;
            split2(vv.x, vv.y, h0, l0); split2(vv.z, vv.w, h1, l1);
            Vhw[r * WSTR + 2 * c] = h0; Vhw[r * WSTR + 2 * c + 1] = h1;
            Vlw[r * WSTR + 2 * c] = l0; Vlw[r * WSTR + 2 * c + 1] = l1;
        }
        __syncthreads();

        const bool diag = (kt == qtile);
        const int npmax = diag ? warp : 3;

        float s[32];
        #pragma unroll
        for (int i = 0; i < 32; ++i) s[i] = 0.f;
        #pragma unroll
        for (int ks = 0; ks < 4; ++ks) {
            for (int np = 0; np <= npmax; ++np) {
                int roff = (np * 16 + mi1 * 8 + r8) * STR + ks * 16 + mi0 * 8;
                unsigned bh4[4], bl4[4];
                ldm_x4(bh4, Kh + roff);
                ldm_x4(bl4, Kl + roff);
                mma3(&s[(np * 2) * 4],     Qh[ks], Ql[ks], bh4[0], bh4[1], bl4[0], bl4[1]);
                mma3(&s[(np * 2 + 1) * 4], Qh[ks], Ql[ks], bh4[2], bh4[3], bl4[2], bl4[3]);
            }
        }
        #pragma unroll
        for (int nt = 0; nt < 8; ++nt)
            #pragma unroll
            for (int j = 0; j < 4; ++j) {
                int rr = qt0 + wr0 + g + (j >> 1) * 8;
                int cc = kt * 64 + nt * 8 + 2 * tg + (j & 1);
                float v = s[nt * 4 + j] * sc;
                if (diag && cc > rr) v = -1e30f;
                s[nt * 4 + j] = v;
            }
        #pragma unroll
        for (int h2 = 0; h2 < 2; ++h2) {
            float mx = -1e30f;
            #pragma unroll
            for (int nt = 0; nt < 8; ++nt) {
                mx = fmaxf(mx, s[nt * 4 + h2 * 2 + 0]);
                mx = fmaxf(mx, s[nt * 4 + h2 * 2 + 1]);
            }
            mx = fmaxf(mx, __shfl_xor_sync(0xffffffffu, mx, 1));
            mx = fmaxf(mx, __shfl_xor_sync(0xffffffffu, mx, 2));
            float mn = fmaxf(m2[h2], mx);
            float alpha = fast_exp2(m2[h2] - mn);
            m2[h2] = mn;
            float rs = 0.f;
            #pragma unroll
            for (int nt = 0; nt < 8; ++nt) {
                float p0 = fast_exp2(s[nt * 4 + h2 * 2 + 0] - mn);
                float p1 = fast_exp2(s[nt * 4 + h2 * 2 + 1] - mn);
                s[nt * 4 + h2 * 2 + 0] = p0;
                s[nt * 4 + h2 * 2 + 1] = p1;
                rs += p0 + p1;
            }
            rs += __shfl_xor_sync(0xffffffffu, rs, 1);
            rs += __shfl_xor_sync(0xffffffffu, rs, 2);
            l2[h2] = l2[h2] * alpha + rs;
            #pragma unroll
            for (int nt = 0; nt < 8; ++nt) {
                O[nt * 4 + h2 * 2 + 0] *= alpha;
                O[nt * 4 + h2 * 2 + 1] *= alpha;
            }
        }
        const int ksmax = diag ? warp : 3;
        #pragma unroll
        for (int ks = 0; ks < 4; ++ks) {
            if (ks > ksmax) break;
            unsigned pah[4], pal[4];
            split2(s[8 * ks + 0], s[8 * ks + 1], pah[0], pal[0]);
            split2(s[8 * ks + 2], s[8 * ks + 3], pah[1], pal[1]);
            split2(s[8 * ks + 4], s[8 * ks + 5], pah[2], pal[2]);
            split2(s[8 * ks + 6], s[8 * ks + 7], pah[3], pal[3]);
            #pragma unroll
            for (int np = 0; np < 4; ++np) {
                int roff = (ks * 16 + mi0 * 8 + r8) * STR + np * 16 + mi1 * 8;
                unsigned vh4[4], vl4[4];
                ldm_x4_t(vh4, Vh + roff);
                ldm_x4_t(vl4, Vl + roff);
                mma3(&O[(np * 2) * 4],     pah, pal, vh4[0], vh4[1], vl4[0], vl4[1]);
                mma3(&O[(np * 2 + 1) * 4], pah, pal, vh4[2], vh4[3], vl4[2], vl4[3]);
            }
        }
    }

    float inv0 = 1.f / l2[0];
    float inv1 = 1.f / l2[1];
    int r_lo = qt0 + wr0 + g;
    int r_hi = r_lo + 8;
    size_t base_lo = ((size_t)(b * NT + r_lo) * 8 + h) * 64;
    size_t base_hi = ((size_t)(b * NT + r_hi) * 8 + h) * 64;
    #pragma unroll
    for (int nt = 0; nt < 8; ++nt) {
        int col = nt * 8 + 2 * tg;
        *(float2*)&g_attn[base_lo + col] =
            make_float2(O[nt*4+0] * inv0, O[nt*4+1] * inv0);
        *(float2*)&g_attn[base_hi + col] =
            make_float2(O[nt*4+2] * inv1, O[nt*4+3] * inv1);
    }
}

// ---------------- K4: logits[t] = E16[ids[t]] + attn_row @ C ----------------
// 8 tokens/block; C in smem (17-stride, conflict-free); shfl reduction.
__global__ __launch_bounds__(256) void k_final(const int* __restrict__ ids,
                                               float* __restrict__ out) {
    __shared__ float Cs[DMODEL * 17];   // 34816 B
    __shared__ float xa[DMODEL];
    int tid = threadIdx.x;
    for (int i = tid; i < DMODEL * NVOC; i += 256) {
        int d = i >> 4, v = i & 15;
        Cs[d * 17 + v] = g_C[i];
    }
    int v = tid >> 4, ch = tid & 15;
    int t0 = blockIdx.x * 8;
    __syncthreads();
    for (int tt = 0; tt < 8; ++tt) {
        int t = t0 + tt;
        for (int i = tid; i < DMODEL; i += 256)
            xa[i] = g_attn[(size_t)t * DMODEL + i];
        __syncthreads();
        float acc = 0.f;
        #pragma unroll
        for (int j = 0; j < 32; ++j) {
            int d = j * 16 + ch;
            acc += xa[d] * Cs[d * 17 + v];
        }
        acc += __shfl_xor_sync(0xffffffffu, acc, 1);
        acc += __shfl_xor_sync(0xffffffffu, acc, 2);
        acc += __shfl_xor_sync(0xffffffffu, acc, 4);
        acc += __shfl_xor_sync(0xffffffffu, acc, 8);
        if (ch == 0)
            out[(size_t)t * NVOC + v] = acc + g_E16[ids[t] * NVOC + v];
        __syncthreads();
    }
}

// ---------------- launch ----------------
extern "C" void kernel_launch(void* const* d_in, const int* in_sizes, int n_in,
                              void* d_out, int out_size) {
    const int*   ids    = (const int*)d_in[0];
    const float* embed  = (const float*)d_in[1];
    const float* ln_g   = (const float*)d_in[2];
    const float* ln_b   = (const float*)d_in[3];
    const float* pq     = (const float*)d_in[4];
    const float* gq     = (const float*)d_in[5];
    const float* pk     = (const float*)d_in[6];
    const float* gk     = (const float*)d_in[7];
    const float* pv     = (const float*)d_in[8];
    const float* gv     = (const float*)d_in[9];
    const float* w1     = (const float*)d_in[10];
    const float* w2     = (const float*)d_in[11];
    const float* o_w    = (const float*)d_in[12];
    const float* head_w = (const float*)d_in[13];
    float* out = (float*)d_out;

    // side stream + fork/join events for k_prep_cn (independent of compose/attn;
    // only k_final consumes g_C/g_E16). Created once on the first (uncaptured)
    // correctness call; same launch sequence every call.
    static cudaStream_t s2 = nullptr;
    static cudaEvent_t evF = nullptr, evJ = nullptr;
    if (s2 == nullptr) {
        cudaStreamCreateWithFlags(&s2, cudaStreamNonBlocking);
        cudaEventCreateWithFlags(&evF, cudaEventDisableTiming);
        cudaEventCreateWithFlags(&evJ, cudaEventDisableTiming);
    }

    const int smem_compose = 8 * PLH * 2 + 3 * 64 * 16 * 4;  // 86016
    const int smem_attn    = 4 * PLH * 2;                    // 36864
    cudaFuncSetAttribute(k_compose, cudaFuncAttributeMaxDynamicSharedMemorySize, smem_compose);
    cudaFuncSetAttribute(k_attn,    cudaFuncAttributeMaxDynamicSharedMemorySize, smem_attn);

    // fork: k_prep_cn runs concurrently on the side stream
    cudaEventRecord(evF, 0);
    cudaStreamWaitEvent(s2, evF, 0);
    k_prep_cn<<<3, 256, 0, s2>>>(o_w, head_w, embed);
    cudaEventRecord(evJ, s2);

    // main stream: prep_w -> embed_ln -> compose -> attn
    k_prep_w<<<NP * 2048 / 256, 256>>>(w1, w2);
    k_embed_ln<<<NTOK, 128>>>(ids, embed, ln_g, ln_b);
    k_compose<<<NTH / 64, 256, smem_compose>>>(pq, gq, pk, gk, pv, gv);
    dim3 ag(NT / 64, NB * NHEAD);
    k_attn<<<ag, 128, smem_attn>>>();

    // join before k_final (consumes g_C / g_E16)
    cudaStreamWaitEvent(0, evJ, 0);
    k_final<<<NTOK / 8, 256>>>(ids, out);
}